// round 14
// baseline (speedup 1.0000x reference)
#include <cuda_runtime.h>
#include <cstdint>
#include <math.h>

// CapsuleLayer: u_hat[b,c,r,o] = sum_i W[c,r,o,i]*x[b,r,i]; out = squash over o.
// B=256, C=10, R=1152, O=16, I=8.
//
// R12 structure (proven 53.3us) with finer b-tiling for occupancy:
//   Block = (32 routes x 8 batches), 128 threads, loops 5 capsule-pairs (c, c+5).
//   thread <-> (route rr = tid/4, o-quad op = tid%4); both capsules' W in regs.
//   x tile in smem (48B route stride -> conflict-free 4-lane-broadcast LDS.128);
//   one x-LDS pair feeds BOTH capsules. f32x2 packed dots, single-MUFU squash,
//   two warp-contiguous 512B STG.128 per iteration.
// Grid 36x32 = 1152 blocks -> ~5 blocks/SM resident (reg-limited), occ ~31%.

#define NUM_CAPSULES 10
#define NUM_ROUTES   1152
#define IN_CH        8
#define OUT_CH       16
#define RT           32     // routes per block
#define BCHUNKS      32
#define BCHUNK_LEN   8      // 256 / BCHUNKS
#define RSTRIDE_F    12     // floats per route row in smem (48B, bank-swizzle)
#define CPAIR        5      // capsule pair stride (c, c+5)

__device__ __forceinline__ uint64_t f2mul(uint64_t a, uint64_t b)
{
    uint64_t d;
    asm("mul.rn.f32x2 %0, %1, %2;" : "=l"(d) : "l"(a), "l"(b));
    return d;
}
__device__ __forceinline__ uint64_t f2fma(uint64_t a, uint64_t b, uint64_t c)
{
    uint64_t d;
    asm("fma.rn.f32x2 %0, %1, %2, %3;" : "=l"(d) : "l"(a), "l"(b), "l"(c));
    return d;
}
__device__ __forceinline__ float f2hsum(uint64_t v)
{
    float lo, hi;
    asm("mov.b64 {%0, %1}, %2;" : "=f"(lo), "=f"(hi) : "l"(v));
    return lo + hi;
}

__device__ __forceinline__ float dot8p(const ulonglong2 wa, const ulonglong2 wb,
                                       const ulonglong2 xa, const ulonglong2 xb)
{
    uint64_t t = f2mul(wa.x, xa.x);
    t = f2fma(wa.y, xa.y, t);
    t = f2fma(wb.x, xb.x, t);
    t = f2fma(wb.y, xb.y, t);
    return f2hsum(t);
}

__global__ __launch_bounds__(128) void capsule_kernel(
    const float* __restrict__ x,   // [B, R, 8]
    const float* __restrict__ W,   // [C, R, 16, 8]
    float* __restrict__ out)       // [B, C, R, 16]
{
    __shared__ float x_s[BCHUNK_LEN * RT * RSTRIDE_F];   // 12 KB

    const int tid = threadIdx.x;
    const int rr  = tid >> 2;          // 0..31
    const int op  = tid & 3;           // 0..3  (o = 4*op .. 4*op+3)
    const int r0  = blockIdx.x * RT;
    const int r   = r0 + rr;
    const int b0  = blockIdx.y * BCHUNK_LEN;

    const size_t XB = (size_t)NUM_ROUTES * IN_CH;                   // x batch stride
    const size_t OB = (size_t)NUM_CAPSULES * NUM_ROUTES * OUT_CH;   // out batch stride

    // ---- Stage x tile: 8 b x 32 r x 2 float4, fully coalesced global reads. ----
#pragma unroll
    for (int it = 0; it < (BCHUNK_LEN * RT * 2) / 128; it++) {
        const int idx = it * 128 + tid;          // 0..511
        const int bb  = idx >> 6;                // /64
        const int rem = idx & 63;
        const int rs  = rem >> 1;                // route within tile
        const int j   = rem & 1;                 // float4 half
        const float4 v = *reinterpret_cast<const float4*>(
            x + (size_t)(b0 + bb) * XB + (size_t)(r0 + rs) * IN_CH + j * 4);
        *reinterpret_cast<float4*>(
            x_s + bb * (RT * RSTRIDE_F) + rs * RSTRIDE_F + j * 4) = v;
    }
    __syncthreads();

    const float* xrow = x_s + rr * RSTRIDE_F;    // this thread-group's route

    const size_t w_step = (size_t)NUM_ROUTES * OUT_CH * IN_CH;      // per-capsule W stride
    const float* Wp = W + (((size_t)r) * OUT_CH + op * 4) * IN_CH;  // c = 0
    const size_t o_base0 = ((size_t)r) * OUT_CH + op * 4;           // c = 0

#pragma unroll 1
    for (int cc = 0; cc < CPAIR; cc++) {
        // Both capsules' W (2 x 32 floats) -> registers; 16 LDG.128 in flight.
        const ulonglong2* Wg0 = reinterpret_cast<const ulonglong2*>(Wp + (size_t)cc * w_step);
        const ulonglong2* Wg1 = reinterpret_cast<const ulonglong2*>(Wp + (size_t)(cc + CPAIR) * w_step);
        ulonglong2 w0[8], w1[8];
#pragma unroll
        for (int j = 0; j < 8; j++) w0[j] = Wg0[j];
#pragma unroll
        for (int j = 0; j < 8; j++) w1[j] = Wg1[j];

        const size_t o_baseA = o_base0 + (size_t)cc * (NUM_ROUTES * OUT_CH);
        const size_t o_baseB = o_base0 + (size_t)(cc + CPAIR) * (NUM_ROUTES * OUT_CH);

#pragma unroll 2
        for (int bb = 0; bb < BCHUNK_LEN; bb++) {
            const ulonglong2 xa = *reinterpret_cast<const ulonglong2*>(
                xrow + bb * (RT * RSTRIDE_F));
            const ulonglong2 xb = *reinterpret_cast<const ulonglong2*>(
                xrow + bb * (RT * RSTRIDE_F) + 4);

            // ---- capsule cc ----
            float a0 = dot8p(w0[0], w0[1], xa, xb);
            float a1 = dot8p(w0[2], w0[3], xa, xb);
            float a2 = dot8p(w0[4], w0[5], xa, xb);
            float a3 = dot8p(w0[6], w0[7], xa, xb);
            // ---- capsule cc+5 ----
            float e0 = dot8p(w1[0], w1[1], xa, xb);
            float e1 = dot8p(w1[2], w1[3], xa, xb);
            float e2 = dot8p(w1[4], w1[5], xa, xb);
            float e3 = dot8p(w1[6], w1[7], xa, xb);

            float sqA = a0 * a0;
            sqA = fmaf(a1, a1, sqA);
            sqA = fmaf(a2, a2, sqA);
            sqA = fmaf(a3, a3, sqA);
            float sqB = e0 * e0;
            sqB = fmaf(e1, e1, sqB);
            sqB = fmaf(e2, e2, sqB);
            sqB = fmaf(e3, e3, sqB);

            sqA += __shfl_xor_sync(0xFFFFFFFFu, sqA, 1);
            sqB += __shfl_xor_sync(0xFFFFFFFFu, sqB, 1);
            sqA += __shfl_xor_sync(0xFFFFFFFFu, sqA, 2);
            sqB += __shfl_xor_sync(0xFFFFFFFFu, sqB, 2);

            // squash: scale = sq/(1+sq)/sqrt(sq+1e-9) = sq*rsqrt((sq+1e-9)*(1+sq)^2)
            const float oplA   = 1.0f + sqA;
            const float scaleA = sqA * rsqrtf((sqA + 1e-9f) * (oplA * oplA));
            const float oplB   = 1.0f + sqB;
            const float scaleB = sqB * rsqrtf((sqB + 1e-9f) * (oplB * oplB));

            float* ob = out + (size_t)(b0 + bb) * OB;
            *reinterpret_cast<float4*>(ob + o_baseA) =
                make_float4(a0 * scaleA, a1 * scaleA, a2 * scaleA, a3 * scaleA);
            *reinterpret_cast<float4*>(ob + o_baseB) =
                make_float4(e0 * scaleB, e1 * scaleB, e2 * scaleB, e3 * scaleB);
        }
    }
}

extern "C" void kernel_launch(void* const* d_in, const int* in_sizes, int n_in,
                              void* d_out, int out_size)
{
    const float* x = (const float*)d_in[0];   // [B, 1152, 8]
    const float* W = (const float*)d_in[1];   // [1, 10, 1152, 16, 8]
    float* out = (float*)d_out;               // [B, 10, 1152, 16]

    dim3 grid(NUM_ROUTES / RT, BCHUNKS);      // 36 x 32 = 1152 blocks
    dim3 block(128);
    capsule_kernel<<<grid, block>>>(x, W, out);
}

// round 15
// speedup vs baseline: 1.1761x; 1.1761x over previous
#include <cuda_runtime.h>
#include <cstdint>
#include <math.h>

// CapsuleLayer: u_hat[b,c,r,o] = sum_i W[c,r,o,i]*x[b,r,i]; out = squash over o.
// B=256, C=10, R=1152, O=16, I=8.
//
// R12 compute structure + coalesced W path:
//   Block = (32 routes x 16 batches), 128 threads, loops 5 capsule-pairs (c,c+5).
//   thread <-> (route rr = tid/4, o-quad op = tid%4).
//   Per pair: W (2 x 16KB) staged global->smem COALESCED (4-wf LDG.128), then
//   per-thread 32-float block read via LDS.128 from 144B-padded slots:
//   column (lane+j)%8 -> exactly 4 lanes/column -> 4-wavefront floor
//   (vs 32-wavefront scattered LDG of the old path).
//   x read directly from global (4-lane broadcast, 2-wf coalesced LDG.128).
//   f32x2 packed dots, 4 shfl + single-MUFU squash, two 512B-contiguous STG.128.
// Grid 36x16 = 576 blocks; smem 36.9KB; ~5 blocks/SM.

#define NUM_CAPSULES 10
#define NUM_ROUTES   1152
#define IN_CH        8
#define OUT_CH       16
#define RT           32     // routes per block
#define BCHUNKS      16
#define BCHUNK_LEN   16     // 256 / BCHUNKS
#define CPAIR        5      // capsule pair stride (c, c+5)
#define WSLOT_F      36     // floats per 144B padded W slot (128B data + 16B pad)

__device__ __forceinline__ uint64_t f2mul(uint64_t a, uint64_t b)
{
    uint64_t d;
    asm("mul.rn.f32x2 %0, %1, %2;" : "=l"(d) : "l"(a), "l"(b));
    return d;
}
__device__ __forceinline__ uint64_t f2fma(uint64_t a, uint64_t b, uint64_t c)
{
    uint64_t d;
    asm("fma.rn.f32x2 %0, %1, %2, %3;" : "=l"(d) : "l"(a), "l"(b), "l"(c));
    return d;
}
__device__ __forceinline__ float f2hsum(uint64_t v)
{
    float lo, hi;
    asm("mov.b64 {%0, %1}, %2;" : "=f"(lo), "=f"(hi) : "l"(v));
    return lo + hi;
}

__device__ __forceinline__ float dot8p(const ulonglong2 wa, const ulonglong2 wb,
                                       const ulonglong2 xa, const ulonglong2 xb)
{
    uint64_t t = f2mul(wa.x, xa.x);
    t = f2fma(wa.y, xa.y, t);
    t = f2fma(wb.x, xb.x, t);
    t = f2fma(wb.y, xb.y, t);
    return f2hsum(t);
}

__global__ __launch_bounds__(128) void capsule_kernel(
    const float* __restrict__ x,   // [B, R, 8]
    const float* __restrict__ W,   // [C, R, 16, 8]
    float* __restrict__ out)       // [B, C, R, 16]
{
    // 256 slots (2 capsules x 128 threads) x 36 floats (144B) = 36,864B.
    __shared__ float w_s[256 * WSLOT_F];

    const int tid = threadIdx.x;
    const int rr  = tid >> 2;          // 0..31
    const int op  = tid & 3;           // 0..3  (o = 4*op .. 4*op+3)
    const int r0  = blockIdx.x * RT;
    const int r   = r0 + rr;
    const int b0  = blockIdx.y * BCHUNK_LEN;

    const size_t XB = (size_t)NUM_ROUTES * IN_CH;                   // x batch stride
    const size_t OB = (size_t)NUM_CAPSULES * NUM_ROUTES * OUT_CH;   // out batch stride
    const size_t w_step = (size_t)NUM_ROUTES * OUT_CH * IN_CH;      // per-capsule W stride

    const size_t x_row   = (size_t)r * IN_CH;
    const size_t o_base0 = ((size_t)r) * OUT_CH + op * 4;           // c = 0

#pragma unroll 1
    for (int cc = 0; cc < CPAIR; cc++) {
        __syncthreads();   // protect previous iteration's smem reads

        // ---- Stage both capsules' W slice (32 routes) into smem, coalesced. ----
#pragma unroll
        for (int q = 0; q < 2; q++) {
            const float4* src = reinterpret_cast<const float4*>(
                W + (size_t)(cc + q * CPAIR) * w_step
                  + (size_t)r0 * (OUT_CH * IN_CH));     // 1024 contiguous float4
#pragma unroll
            for (int k = 0; k < 8; k++) {
                const int g   = k * 128 + tid;          // 0..1023
                const float4 v = src[g];
                const int t_d = g >> 3;                 // dest slot within capsule (rr*4+op)
                const int j   = g & 7;                  // 16B chunk
                *reinterpret_cast<float4*>(
                    w_s + (q * 128 + t_d) * WSLOT_F + j * 4) = v;
            }
        }
        __syncthreads();

        // ---- Load this thread's W blocks from smem (4-wavefront LDS.128). ----
        ulonglong2 w0[8], w1[8];
#pragma unroll
        for (int j = 0; j < 8; j++)
            w0[j] = *reinterpret_cast<const ulonglong2*>(w_s + tid * WSLOT_F + j * 4);
#pragma unroll
        for (int j = 0; j < 8; j++)
            w1[j] = *reinterpret_cast<const ulonglong2*>(w_s + (128 + tid) * WSLOT_F + j * 4);

        const size_t o_baseA = o_base0 + (size_t)cc * (NUM_ROUTES * OUT_CH);
        const size_t o_baseB = o_base0 + (size_t)(cc + CPAIR) * (NUM_ROUTES * OUT_CH);

#pragma unroll 2
        for (int bb = 0; bb < BCHUNK_LEN; bb++) {
            const ulonglong2* xg = reinterpret_cast<const ulonglong2*>(
                x + (size_t)(b0 + bb) * XB + x_row);
            const ulonglong2 xa = xg[0];
            const ulonglong2 xb = xg[1];

            // ---- capsule cc ----
            float a0 = dot8p(w0[0], w0[1], xa, xb);
            float a1 = dot8p(w0[2], w0[3], xa, xb);
            float a2 = dot8p(w0[4], w0[5], xa, xb);
            float a3 = dot8p(w0[6], w0[7], xa, xb);
            // ---- capsule cc+5 ----
            float e0 = dot8p(w1[0], w1[1], xa, xb);
            float e1 = dot8p(w1[2], w1[3], xa, xb);
            float e2 = dot8p(w1[4], w1[5], xa, xb);
            float e3 = dot8p(w1[6], w1[7], xa, xb);

            float sqA = a0 * a0;
            sqA = fmaf(a1, a1, sqA);
            sqA = fmaf(a2, a2, sqA);
            sqA = fmaf(a3, a3, sqA);
            float sqB = e0 * e0;
            sqB = fmaf(e1, e1, sqB);
            sqB = fmaf(e2, e2, sqB);
            sqB = fmaf(e3, e3, sqB);

            sqA += __shfl_xor_sync(0xFFFFFFFFu, sqA, 1);
            sqB += __shfl_xor_sync(0xFFFFFFFFu, sqB, 1);
            sqA += __shfl_xor_sync(0xFFFFFFFFu, sqA, 2);
            sqB += __shfl_xor_sync(0xFFFFFFFFu, sqB, 2);

            // squash: scale = sq/(1+sq)/sqrt(sq+1e-9) = sq*rsqrt((sq+1e-9)*(1+sq)^2)
            const float oplA   = 1.0f + sqA;
            const float scaleA = sqA * rsqrtf((sqA + 1e-9f) * (oplA * oplA));
            const float oplB   = 1.0f + sqB;
            const float scaleB = sqB * rsqrtf((sqB + 1e-9f) * (oplB * oplB));

            float* ob = out + (size_t)(b0 + bb) * OB;
            *reinterpret_cast<float4*>(ob + o_baseA) =
                make_float4(a0 * scaleA, a1 * scaleA, a2 * scaleA, a3 * scaleA);
            *reinterpret_cast<float4*>(ob + o_baseB) =
                make_float4(e0 * scaleB, e1 * scaleB, e2 * scaleB, e3 * scaleB);
        }
    }
}

extern "C" void kernel_launch(void* const* d_in, const int* in_sizes, int n_in,
                              void* d_out, int out_size)
{
    const float* x = (const float*)d_in[0];   // [B, 1152, 8]
    const float* W = (const float*)d_in[1];   // [1, 10, 1152, 16, 8]
    float* out = (float*)d_out;               // [B, 10, 1152, 16]

    dim3 grid(NUM_ROUTES / RT, BCHUNKS);      // 36 x 16 = 576 blocks
    dim3 block(128);
    capsule_kernel<<<grid, block>>>(x, W, out);
}

// round 16
// speedup vs baseline: 1.3218x; 1.1239x over previous
#include <cuda_runtime.h>
#include <cstdint>
#include <math.h>

// CapsuleLayer: u_hat[b,c,r,o] = sum_i W[c,r,o,i]*x[b,r,i]; out = squash over o.
// B=256, C=10, R=1152, O=16, I=8.
//
// Combines the two proven wins:
//   R9/R12: x tile in smem (48B route stride, conflict-free 4-lane-broadcast LDS)
//   R15:    W staged global->smem COALESCED, then 4-wf-floor LDS from 144B slots
// Block = (32 routes x 16 batches), 128 threads, loops over 10 capsules:
//   per capsule: stage W[c, r0:r0+32] (16KB) coalesced -> padded smem slots,
//   sync, pull 32 W floats/thread via 8x LDS.128, then 16-b mainloop
//   (x LDS + f32x2 dots + 2 shfl + single-MUFU squash + 512B-contiguous STG.128).
// Smem 42.4KB, ~5 blocks/SM. Grid 36x16 = 576 blocks.

#define NUM_CAPSULES 10
#define NUM_ROUTES   1152
#define IN_CH        8
#define OUT_CH       16
#define RT           32     // routes per block
#define BCHUNKS      16
#define BCHUNK_LEN   16     // 256 / BCHUNKS
#define RSTRIDE_F    12     // floats per route row in x smem (48B, bank-swizzle)
#define WSLOT_F      36     // floats per 144B padded W slot (128B data + 16B pad)

__device__ __forceinline__ uint64_t f2mul(uint64_t a, uint64_t b)
{
    uint64_t d;
    asm("mul.rn.f32x2 %0, %1, %2;" : "=l"(d) : "l"(a), "l"(b));
    return d;
}
__device__ __forceinline__ uint64_t f2fma(uint64_t a, uint64_t b, uint64_t c)
{
    uint64_t d;
    asm("fma.rn.f32x2 %0, %1, %2, %3;" : "=l"(d) : "l"(a), "l"(b), "l"(c));
    return d;
}
__device__ __forceinline__ float f2hsum(uint64_t v)
{
    float lo, hi;
    asm("mov.b64 {%0, %1}, %2;" : "=f"(lo), "=f"(hi) : "l"(v));
    return lo + hi;
}

__device__ __forceinline__ float dot8p(const ulonglong2 wa, const ulonglong2 wb,
                                       const ulonglong2 xa, const ulonglong2 xb)
{
    uint64_t t = f2mul(wa.x, xa.x);
    t = f2fma(wa.y, xa.y, t);
    t = f2fma(wb.x, xb.x, t);
    t = f2fma(wb.y, xb.y, t);
    return f2hsum(t);
}

__global__ __launch_bounds__(128) void capsule_kernel(
    const float* __restrict__ x,   // [B, R, 8]
    const float* __restrict__ W,   // [C, R, 16, 8]
    float* __restrict__ out)       // [B, C, R, 16]
{
    __shared__ float x_s[BCHUNK_LEN * RT * RSTRIDE_F];   // 24 KB
    __shared__ float w_s[128 * WSLOT_F];                 // 18 KB

    const int tid = threadIdx.x;
    const int rr  = tid >> 2;          // 0..31
    const int op  = tid & 3;           // 0..3  (o = 4*op .. 4*op+3)
    const int r0  = blockIdx.x * RT;
    const int r   = r0 + rr;
    const int b0  = blockIdx.y * BCHUNK_LEN;

    const size_t XB = (size_t)NUM_ROUTES * IN_CH;                   // x batch stride
    const size_t OB = (size_t)NUM_CAPSULES * NUM_ROUTES * OUT_CH;   // out batch stride
    const size_t w_step = (size_t)NUM_ROUTES * OUT_CH * IN_CH;      // per-capsule W stride

    // ---- Stage x tile: 16 b x 32 r x 2 float4, fully coalesced global reads. ----
#pragma unroll
    for (int it = 0; it < (BCHUNK_LEN * RT * 2) / 128; it++) {
        const int idx = it * 128 + tid;          // 0..1023
        const int bb  = idx >> 6;                // /64
        const int rem = idx & 63;
        const int rs  = rem >> 1;                // route within tile
        const int j   = rem & 1;                 // float4 half
        const float4 v = *reinterpret_cast<const float4*>(
            x + (size_t)(b0 + bb) * XB + (size_t)(r0 + rs) * IN_CH + j * 4);
        *reinterpret_cast<float4*>(
            x_s + bb * (RT * RSTRIDE_F) + rs * RSTRIDE_F + j * 4) = v;
    }

    const float* xrow = x_s + rr * RSTRIDE_F;    // this thread-group's route
    const size_t o_base0 = ((size_t)r) * OUT_CH + op * 4;  // c = 0

#pragma unroll 1
    for (int c = 0; c < NUM_CAPSULES; c++) {
        __syncthreads();   // protect previous iteration's w_s reads (and x_s staging, iter 0)

        // ---- Stage W[c, r0:r0+32] (1024 float4) into padded smem slots, coalesced. ----
        const float4* src = reinterpret_cast<const float4*>(
            W + (size_t)c * w_step + (size_t)r0 * (OUT_CH * IN_CH));
#pragma unroll
        for (int k = 0; k < 8; k++) {
            const int g   = k * 128 + tid;       // 0..1023
            const float4 v = src[g];
            const int t_d = g >> 3;              // dest slot (= rr*4+op of owner)
            const int j   = g & 7;               // 16B chunk
            *reinterpret_cast<float4*>(w_s + t_d * WSLOT_F + j * 4) = v;
        }
        __syncthreads();

        // ---- This thread's 32 W floats from smem (4-wavefront-floor LDS.128). ----
        ulonglong2 w[8];
#pragma unroll
        for (int j = 0; j < 8; j++)
            w[j] = *reinterpret_cast<const ulonglong2*>(w_s + tid * WSLOT_F + j * 4);

        const size_t o_base = o_base0 + (size_t)c * (NUM_ROUTES * OUT_CH);

#pragma unroll 2
        for (int bb = 0; bb < BCHUNK_LEN; bb++) {
            const ulonglong2 xa = *reinterpret_cast<const ulonglong2*>(
                xrow + bb * (RT * RSTRIDE_F));
            const ulonglong2 xb = *reinterpret_cast<const ulonglong2*>(
                xrow + bb * (RT * RSTRIDE_F) + 4);

            float u0 = dot8p(w[0], w[1], xa, xb);
            float u1 = dot8p(w[2], w[3], xa, xb);
            float u2 = dot8p(w[4], w[5], xa, xb);
            float u3 = dot8p(w[6], w[7], xa, xb);

            float sq = u0 * u0;
            sq = fmaf(u1, u1, sq);
            sq = fmaf(u2, u2, sq);
            sq = fmaf(u3, u3, sq);
            sq += __shfl_xor_sync(0xFFFFFFFFu, sq, 1);
            sq += __shfl_xor_sync(0xFFFFFFFFu, sq, 2);

            // squash: scale = sq/(1+sq)/sqrt(sq+1e-9) = sq*rsqrt((sq+1e-9)*(1+sq)^2)
            const float opl   = 1.0f + sq;
            const float scale = sq * rsqrtf((sq + 1e-9f) * (opl * opl));

            float4* og = reinterpret_cast<float4*>(
                out + (size_t)(b0 + bb) * OB + o_base);
            og[0] = make_float4(u0 * scale, u1 * scale, u2 * scale, u3 * scale);
        }
    }
}

extern "C" void kernel_launch(void* const* d_in, const int* in_sizes, int n_in,
                              void* d_out, int out_size)
{
    const float* x = (const float*)d_in[0];   // [B, 1152, 8]
    const float* W = (const float*)d_in[1];   // [1, 10, 1152, 16, 8]
    float* out = (float*)d_out;               // [B, 10, 1152, 16]

    dim3 grid(NUM_ROUTES / RT, BCHUNKS);      // 36 x 16 = 576 blocks
    dim3 block(128);
    capsule_kernel<<<grid, block>>>(x, W, out);
}